// round 6
// baseline (speedup 1.0000x reference)
#include <cuda_runtime.h>

#define T_STEPS 2048
#define B_SIZE  4096
#define OUTD    4
#define BLOCK_THREADS 128
#define EPT 2              // elements per thread

typedef unsigned long long u64;

// ---------- packed f32x2 helpers (sm_100a) ----------
__device__ __forceinline__ u64 pack2(float lo, float hi) {
    u64 r;
    asm("mov.b64 %0, {%1, %2};"
        : "=l"(r) : "r"(__float_as_uint(lo)), "r"(__float_as_uint(hi)));
    return r;
}
__device__ __forceinline__ float hadd2(u64 v) {
    unsigned a, b;
    asm("mov.b64 {%0, %1}, %2;" : "=r"(a), "=r"(b) : "l"(v));
    return __uint_as_float(a) + __uint_as_float(b);
}
__device__ __forceinline__ u64 fma2(u64 a, u64 b, u64 c) {
    u64 d;
    asm("fma.rn.f32x2 %0, %1, %2, %3;" : "=l"(d) : "l"(a), "l"(b), "l"(c));
    return d;
}
__device__ __forceinline__ u64 add2(u64 a, u64 b) {
    u64 d;
    asm("add.rn.f32x2 %0, %1, %2;" : "=l"(d) : "l"(a), "l"(b));
    return d;
}

// ---------- MUFU activations ----------
__device__ __forceinline__ float tanh_mufu(float x) {
    float r; asm("tanh.approx.f32 %0, %1;" : "=f"(r) : "f"(x)); return r;
}
__device__ __forceinline__ float sigmoid_mufu(float x) {
    return fmaf(0.5f, tanh_mufu(0.5f * x), 0.5f);
}

// broadcast 8-group value s into 4 packed pairs (k-pairs 01,23,45,67)
__device__ __forceinline__ void bc_pack(float s, u64 (&p)[4]) {
    float v0 = __shfl_sync(0xffffffffu, s, 0, 8);
    float v1 = __shfl_sync(0xffffffffu, s, 1, 8);
    float v2 = __shfl_sync(0xffffffffu, s, 2, 8);
    float v3 = __shfl_sync(0xffffffffu, s, 3, 8);
    float v4 = __shfl_sync(0xffffffffu, s, 4, 8);
    float v5 = __shfl_sync(0xffffffffu, s, 5, 8);
    float v6 = __shfl_sync(0xffffffffu, s, 6, 8);
    float v7 = __shfl_sync(0xffffffffu, s, 7, 8);
    p[0] = pack2(v0, v1);
    p[1] = pack2(v2, v3);
    p[2] = pack2(v4, v5);
    p[3] = pack2(v6, v7);
}

// tree-shaped packed dot over 8 (4 pairs), seeded; returns horizontal sum
__device__ __forceinline__ float dot8(const u64 (&w)[4], const u64 (&p)[4], u64 seed) {
    u64 a = fma2(w[0], p[0], seed);
    u64 b = fma2(w[1], p[1], 0ULL);
    a = fma2(w[2], p[2], a);
    b = fma2(w[3], p[3], b);
    return hadd2(add2(a, b));
}

__global__ void __launch_bounds__(BLOCK_THREADS, 1)
gru3_fused_kernel(const float* __restrict__ x,
                  const float* __restrict__ Wih0, const float* __restrict__ Whh0,
                  const float* __restrict__ bih0, const float* __restrict__ bhh0,
                  const float* __restrict__ Wih1, const float* __restrict__ Whh1,
                  const float* __restrict__ bih1, const float* __restrict__ bhh1,
                  const float* __restrict__ Wih2, const float* __restrict__ Whh2,
                  const float* __restrict__ bih2, const float* __restrict__ bhh2,
                  const float* __restrict__ fcW,  const float* __restrict__ fcb,
                  float* __restrict__ out)
{
    const int g   = blockIdx.x * BLOCK_THREADS + threadIdx.x;
    const int b0  = g >> 3;       // first batch element; second is b0 + 2048
    const int sub = g & 7;        // hidden unit owned by this lane

    // ---- packed register-resident weights (shared by both elements) ----
    u64 whh0[3][4], whh1[3][4], whh2[3][4];
    u64 wih1[3][4], wih2[3][4];
    u64 wx0[3];

    const float2* Whh0v = (const float2*)Whh0;
    const float2* Whh1v = (const float2*)Whh1;
    const float2* Whh2v = (const float2*)Whh2;
    const float2* Wih1v = (const float2*)Wih1;
    const float2* Wih2v = (const float2*)Wih2;
    const float2* Wih0v = (const float2*)Wih0;

#pragma unroll
    for (int gt = 0; gt < 3; gt++) {
        const int row = gt * 8 + sub;
#pragma unroll
        for (int kk = 0; kk < 4; kk++) {
            float2 a = Whh0v[row * 4 + kk]; whh0[gt][kk] = pack2(a.x, a.y);
            float2 c = Whh1v[row * 4 + kk]; whh1[gt][kk] = pack2(c.x, c.y);
            float2 e = Whh2v[row * 4 + kk]; whh2[gt][kk] = pack2(e.x, e.y);
            float2 d = Wih1v[row * 4 + kk]; wih1[gt][kk] = pack2(d.x, d.y);
            float2 f = Wih2v[row * 4 + kk]; wih2[gt][kk] = pack2(f.x, f.y);
        }
        float2 w0 = Wih0v[row];  // F=2
        wx0[gt] = pack2(w0.x, w0.y);
    }

    // bias seeds (bias lives in lane0 of the packed seed)
    const u64 sR0  = pack2(bih0[sub]     + bhh0[sub],     0.0f);
    const u64 sZ0  = pack2(bih0[8 + sub] + bhh0[8 + sub], 0.0f);
    const u64 sNx0 = pack2(bih0[16 + sub], 0.0f);
    const u64 sNh0 = pack2(bhh0[16 + sub], 0.0f);
    const u64 sR1  = pack2(bih1[sub]     + bhh1[sub],     0.0f);
    const u64 sZ1  = pack2(bih1[8 + sub] + bhh1[8 + sub], 0.0f);
    const u64 sNx1 = pack2(bih1[16 + sub], 0.0f);
    const u64 sNh1 = pack2(bhh1[16 + sub], 0.0f);
    const u64 sR2  = pack2(bih2[sub]     + bhh2[sub],     0.0f);
    const u64 sZ2  = pack2(bih2[8 + sub] + bhh2[8 + sub], 0.0f);
    const u64 sNx2 = pack2(bih2[16 + sub], 0.0f);
    const u64 sNh2 = pack2(bhh2[16 + sub], 0.0f);

    // ---- dual-element recurrence state ----
    float h0[EPT], h1[EPT], h2[EPT], acc[EPT], cx0[EPT], cx1[EPT];
    u64 P0[EPT][4], P1[EPT][4], P2[EPT][4];
#pragma unroll
    for (int e = 0; e < EPT; e++) {
        h0[e] = h1[e] = h2[e] = acc[e] = 0.0f;
#pragma unroll
        for (int k = 0; k < 4; k++) { P0[e][k] = 0ULL; P1[e][k] = 0ULL; P2[e][k] = 0ULL; }
    }

    const float* xp[EPT];
    xp[0] = x + (size_t)b0 * 2;
    xp[1] = x + (size_t)(b0 + 2048) * 2;
#pragma unroll
    for (int e = 0; e < EPT; e++) {
        cx0[e] = __ldg(xp[e]);
        cx1[e] = __ldg(xp[e] + 1);
        xp[e] += B_SIZE * 2;
    }

#pragma unroll 1
    for (int t = 0; t < T_STEPS; t++) {
        // prefetch x(t+1) for both elements (last iter reads in-bounds garbage row t=0 side? no:
        // guard by clamping pointer advance — simply avoid read past end)
        float nx0[EPT], nx1[EPT];
        const bool more = (t + 1 < T_STEPS);
#pragma unroll
        for (int e = 0; e < EPT; e++) {
            const float* p = more ? xp[e] : (xp[e] - B_SIZE * 2);
            nx0[e] = __ldg(p);
            nx1[e] = __ldg(p + 1);
            xp[e] += B_SIZE * 2;
        }

        // ---- phase A: all hh partials (t-1 state), both elements: fully independent ----
        float a0R[EPT], a0Z[EPT], a0Nh[EPT], nxg[EPT];
        float a1Rh[EPT], a1Zh[EPT], a1Nh[EPT];
        float a2Rh[EPT], a2Zh[EPT], a2Nh[EPT];
#pragma unroll
        for (int e = 0; e < EPT; e++) {
            const u64 px = pack2(cx0[e], cx1[e]);
            a0R[e]  = dot8(whh0[0], P0[e], fma2(wx0[0], px, sR0));
            a0Nh[e] = dot8(whh0[2], P0[e], sNh0);
            a0Z[e]  = dot8(whh0[1], P0[e], fma2(wx0[1], px, sZ0));
            nxg[e]  = hadd2(fma2(wx0[2], px, sNx0));
            a1Rh[e] = dot8(whh1[0], P1[e], sR1);
            a1Nh[e] = dot8(whh1[2], P1[e], sNh1);
            a1Zh[e] = dot8(whh1[1], P1[e], sZ1);
            a2Rh[e] = dot8(whh2[0], P2[e], sR2);
            a2Nh[e] = dot8(whh2[2], P2[e], sNh2);
            a2Zh[e] = dot8(whh2[1], P2[e], sZ2);
        }

        // ---- phase B: layer 0 finish + broadcast ----
#pragma unroll
        for (int e = 0; e < EPT; e++) {
            float r = sigmoid_mufu(a0R[e]);
            float z = sigmoid_mufu(a0Z[e]);
            float n = tanh_mufu(fmaf(r, a0Nh[e], nxg[e]));
            h0[e] = fmaf(z, h0[e] - n, n);
            bc_pack(h0[e], P0[e]);
        }

        // ---- phase C: layer 1 ----
#pragma unroll
        for (int e = 0; e < EPT; e++) {
            float r = sigmoid_mufu(dot8(wih1[0], P0[e], 0ULL) + a1Rh[e]);
            float z = sigmoid_mufu(dot8(wih1[1], P0[e], 0ULL) + a1Zh[e]);
            float n = tanh_mufu(fmaf(r, a1Nh[e], dot8(wih1[2], P0[e], sNx1)));
            h1[e] = fmaf(z, h1[e] - n, n);
            bc_pack(h1[e], P1[e]);
        }

        // ---- phase D: layer 2 + accumulate ----
#pragma unroll
        for (int e = 0; e < EPT; e++) {
            float r = sigmoid_mufu(dot8(wih2[0], P1[e], 0ULL) + a2Rh[e]);
            float z = sigmoid_mufu(dot8(wih2[1], P1[e], 0ULL) + a2Zh[e]);
            float n = tanh_mufu(fmaf(r, a2Nh[e], dot8(wih2[2], P1[e], sNx2)));
            h2[e] = fmaf(z, h2[e] - n, n);
            bc_pack(h2[e], P2[e]);
            acc[e] += h2[e];
        }

#pragma unroll
        for (int e = 0; e < EPT; e++) { cx0[e] = nx0[e]; cx1[e] = nx1[e]; }
    }

    // ---- mean over T, then FC (OUT=4), per element ----
#pragma unroll
    for (int e = 0; e < EPT; e++) {
        const float mean = acc[e] * (1.0f / (float)T_STEPS);
        float m[8];
#pragma unroll
        for (int k = 0; k < 8; k++)
            m[k] = __shfl_sync(0xffffffffu, mean, k, 8);

        if (sub < OUTD) {
            float o = __ldg(fcb + sub);
#pragma unroll
            for (int k = 0; k < 8; k++)
                o = fmaf(__ldg(fcW + sub * 8 + k), m[k], o);
            const int bel = b0 + e * 2048;
            out[(size_t)bel * OUTD + sub] = o;
        }
    }
}

extern "C" void kernel_launch(void* const* d_in, const int* in_sizes, int n_in,
                              void* d_out, int out_size)
{
    const float* x    = (const float*)d_in[0];
    const float* Wih0 = (const float*)d_in[1];
    const float* Whh0 = (const float*)d_in[2];
    const float* bih0 = (const float*)d_in[3];
    const float* bhh0 = (const float*)d_in[4];
    const float* Wih1 = (const float*)d_in[5];
    const float* Whh1 = (const float*)d_in[6];
    const float* bih1 = (const float*)d_in[7];
    const float* bhh1 = (const float*)d_in[8];
    const float* Wih2 = (const float*)d_in[9];
    const float* Whh2 = (const float*)d_in[10];
    const float* bih2 = (const float*)d_in[11];
    const float* bhh2 = (const float*)d_in[12];
    const float* fcW  = (const float*)d_in[13];
    const float* fcb  = (const float*)d_in[14];
    float* out = (float*)d_out;

    // 2048 element-pairs * 8 lanes = 16384 threads; 128 blocks of 128
    const int total_threads = (B_SIZE / EPT) * 8;
    const int blocks = total_threads / BLOCK_THREADS;   // 128

    gru3_fused_kernel<<<blocks, BLOCK_THREADS>>>(
        x,
        Wih0, Whh0, bih0, bhh0,
        Wih1, Whh1, bih1, bhh1,
        Wih2, Whh2, bih2, bhh2,
        fcW, fcb, out);
}